// round 15
// baseline (speedup 1.0000x reference)
#include <cuda_runtime.h>

// Problem constants
#define NB   512      // batches
#define NL   512      // stream length
#define NC   8        // channels
#define NSEG 8        // segments per batch (Chen-associative split)
#define SEGLEN 64     // increments per segment (last has 63)
#define SIGSZ 584     // 8 + 64 + 512
#define NINC (NL - 1) // 511
#define SBUF 592      // padded per-warp smem buffer (>= 584 and >= SEGLEN*NC)

// ---------------------------------------------------------------------------
// Fused signature kernel: 1 block = 1 batch, 256 threads = 8 warps.
// Warp g scans segment g. Lane owns pairs (i,j0),(i,j0+1): i=lane>>2,
// j0=(lane&3)*2. Per step only TWO broadcast LDS.128 (d0,d1) hit shared;
// dxi and the dxj pair are selected from the d0/d1 registers with FSEL
// chains (lane-constant predicates hoisted out of the loop) — moves the
// former dxi/dxj LDS traffic onto the idle ALU pipe.
// Per step (old state RHS), m/n shared across the pair:
//   m = dxi/6 + S1h ; n = 3m - S1h (= dxi/2 + S1)
//   c_p = dxj_p*m + S2_p ; S2_p += dxj_p*n ; S3[p][k] += c_p*dx_k ; S1h += dxi/2
// Then 8 partial signatures tree-fold in smem (3 rounds); warp 0 writes out.
// ---------------------------------------------------------------------------

struct SigRegs {
    float A1;        // A1[i]
    float A2[2];     // A2[i,j0], A2[i,j0+1]
    float A3[2][8];  // A3[i,j0,:], A3[i,j0+1,:]
};

__device__ __forceinline__ void sig_store(float* __restrict__ sb,
                                          const SigRegs& S, int i, int j0) {
    if (j0 == 0) sb[i] = S.A1;
    *(float2*)(sb + 8 + i * 8 + j0) = make_float2(S.A2[0], S.A2[1]);
    float* b3 = sb + 72 + (i * 8 + j0) * 8;
    *(float4*)(b3)      = make_float4(S.A3[0][0], S.A3[0][1], S.A3[0][2], S.A3[0][3]);
    *(float4*)(b3 + 4)  = make_float4(S.A3[0][4], S.A3[0][5], S.A3[0][6], S.A3[0][7]);
    *(float4*)(b3 + 8)  = make_float4(S.A3[1][0], S.A3[1][1], S.A3[1][2], S.A3[1][3]);
    *(float4*)(b3 + 12) = make_float4(S.A3[1][4], S.A3[1][5], S.A3[1][6], S.A3[1][7]);
}

// Chen fold, 2-pair layout (B in standard sig layout; old A on RHS)
__device__ __forceinline__ void sig_fold(SigRegs& S, const float* __restrict__ sb,
                                         int i, int j0) {
    const float B1i = sb[i];
    const float2 B1j  = *(const float2*)(sb + j0);
    const float2 B2ij = *(const float2*)(sb + 8 + i * 8 + j0);
    float4 x0 = *(const float4*)(sb);
    float4 x1 = *(const float4*)(sb + 4);
    float4 y0 = *(const float4*)(sb + 8 + j0 * 8);
    float4 y1 = *(const float4*)(sb + 8 + j0 * 8 + 4);
    float4 y2 = *(const float4*)(sb + 8 + j0 * 8 + 8);
    float4 y3 = *(const float4*)(sb + 8 + j0 * 8 + 12);
    const float* b3p = sb + 72 + (i * 8 + j0) * 8;
    float4 z0 = *(const float4*)(b3p);
    float4 z1 = *(const float4*)(b3p + 4);
    float4 z2 = *(const float4*)(b3p + 8);
    float4 z3 = *(const float4*)(b3p + 12);

    float b1v[8]    = {x0.x, x0.y, x0.z, x0.w, x1.x, x1.y, x1.z, x1.w};
    float b2v[2][8] = {{y0.x, y0.y, y0.z, y0.w, y1.x, y1.y, y1.z, y1.w},
                       {y2.x, y2.y, y2.z, y2.w, y3.x, y3.y, y3.z, y3.w}};
    float b3v[2][8] = {{z0.x, z0.y, z0.z, z0.w, z1.x, z1.y, z1.z, z1.w},
                       {z2.x, z2.y, z2.z, z2.w, z3.x, z3.y, z3.z, z3.w}};

    #pragma unroll
    for (int p = 0; p < 2; p++)
        #pragma unroll
        for (int k = 0; k < 8; k++)  // uses OLD A1, A2
            S.A3[p][k] = fmaf(S.A1, b2v[p][k],
                         fmaf(S.A2[p], b1v[k], S.A3[p][k] + b3v[p][k]));
    S.A2[0] = fmaf(S.A1, B1j.x, S.A2[0] + B2ij.x);
    S.A2[1] = fmaf(S.A1, B1j.y, S.A2[1] + B2ij.y);
    S.A1 = S.A1 + B1i;
}

__global__ __launch_bounds__(256) void sig_kernel(const float* __restrict__ path,
                                                  float* __restrict__ out) {
    // Per-warp buffer: SEGLEN*NC=512 increment floats during the scan,
    // reused as a 584-float signature buffer for the fold. 18.5 KB total.
    __shared__ __align__(16) float sdx[NSEG][SBUF];

    const int tid  = threadIdx.x;
    const int g    = tid >> 5;        // warp = segment (0..7)
    const int lane = tid & 31;
    const int i    = lane >> 2;
    const int j0   = (lane & 3) << 1;
    const int batch = blockIdx.x;
    const int t0    = g * SEGLEN;
    const int nsteps = (g == NSEG - 1) ? (NINC - (NSEG - 1) * SEGLEN) : SEGLEN; // 63/64

    // lane-constant select predicates (hoisted out of the step loop)
    const bool b0 = (i & 1) != 0;
    const bool b1 = (i & 2) != 0;
    const bool b2 = (i & 4) != 0;
    const bool q0 = (lane & 1) != 0;   // j0 & 2
    const bool q1 = (lane & 2) != 0;   // j0 & 4

    // ---- stage increments (float4) for this warp's segment ----
    {
        const float4* __restrict__ pb4 =
            (const float4*)(path + (size_t)batch * NL * NC + (size_t)t0 * NC);
        float4* __restrict__ s4 = (float4*)sdx[g];
        const int n4 = nsteps * 2;
        for (int v = lane; v < n4; v += 32) {
            float4 a = pb4[v];
            float4 b = pb4[v + 2];   // +8 floats = next step, same chans
            s4[v] = make_float4(b.x - a.x, b.y - a.y, b.z - a.z, b.w - a.w);
        }
    }
    __syncwarp();

    // ---- sequential scan over this segment (warp-private) ----
    float S1h = 0.f, S20 = 0.f, S21 = 0.f;
    float S3[2][8];
    #pragma unroll
    for (int p = 0; p < 2; p++)
        #pragma unroll
        for (int k = 0; k < 8; k++) S3[p][k] = 0.f;

    const float* __restrict__ dxp = sdx[g];
    #pragma unroll 4
    for (int s = 0; s < nsteps; s++) {
        // the only shared-memory traffic per step: two broadcast LDS.128
        const float4 d0 = *(const float4*)(dxp + s * 8);
        const float4 d1 = *(const float4*)(dxp + s * 8 + 4);

        // dxi = d[i] via 7-FSEL tree (ALU pipe, predicates loop-invariant)
        const float s01 = b0 ? d0.y : d0.x;
        const float s23 = b0 ? d0.w : d0.z;
        const float s45 = b0 ? d1.y : d1.x;
        const float s67 = b0 ? d1.w : d1.z;
        const float s03 = b1 ? s23 : s01;
        const float s47 = b1 ? s67 : s45;
        const float dxi = b2 ? s47 : s03;

        // dxj pair = (d[j0], d[j0+1]) via 6-FSEL tree
        const float jx0 = q0 ? d0.z : d0.x;
        const float jy0 = q0 ? d0.w : d0.y;
        const float jx1 = q0 ? d1.z : d1.x;
        const float jy1 = q0 ? d1.w : d1.y;
        const float dxjx = q1 ? jx1 : jx0;
        const float dxjy = q1 ? jy1 : jy0;

        const float m = fmaf(dxi, 0.16666666666666666f, S1h);
        const float n = fmaf(3.0f, m, -S1h);          // dxi/2 + S1
        const float c0 = fmaf(dxjx, m, S20);
        const float c1 = fmaf(dxjy, m, S21);
        S20 = fmaf(dxjx, n, S20);
        S21 = fmaf(dxjy, n, S21);

        S3[0][0] = fmaf(c0, d0.x, S3[0][0]);
        S3[0][1] = fmaf(c0, d0.y, S3[0][1]);
        S3[0][2] = fmaf(c0, d0.z, S3[0][2]);
        S3[0][3] = fmaf(c0, d0.w, S3[0][3]);
        S3[0][4] = fmaf(c0, d1.x, S3[0][4]);
        S3[0][5] = fmaf(c0, d1.y, S3[0][5]);
        S3[0][6] = fmaf(c0, d1.z, S3[0][6]);
        S3[0][7] = fmaf(c0, d1.w, S3[0][7]);
        S3[1][0] = fmaf(c1, d0.x, S3[1][0]);
        S3[1][1] = fmaf(c1, d0.y, S3[1][1]);
        S3[1][2] = fmaf(c1, d0.z, S3[1][2]);
        S3[1][3] = fmaf(c1, d0.w, S3[1][3]);
        S3[1][4] = fmaf(c1, d1.x, S3[1][4]);
        S3[1][5] = fmaf(c1, d1.y, S3[1][5]);
        S3[1][6] = fmaf(c1, d1.z, S3[1][6]);
        S3[1][7] = fmaf(c1, d1.w, S3[1][7]);

        S1h = fmaf(0.5f, dxi, S1h);
    }

    SigRegs S;
    S.A1 = 2.f * S1h;
    S.A2[0] = S20; S.A2[1] = S21;
    #pragma unroll
    for (int p = 0; p < 2; p++)
        #pragma unroll
        for (int k = 0; k < 8; k++) S.A3[p][k] = S3[p][k];

    // scan reads -> publish writes to the SAME warp-private buffer
    __syncwarp();

    // ---- in-block tree fold ----
    if (g & 1) sig_store(sdx[g], S, i, j0);
    __syncthreads();

    // round 1: 0<-0o1, 2<-2o3, 4<-4o5, 6<-6o7 ; warps 2,6 publish results
    if ((g & 1) == 0) {
        sig_fold(S, sdx[g + 1], i, j0);
        if (g == 2 || g == 6) sig_store(sdx[g], S, i, j0);
    }
    __syncthreads();

    // round 2: 0<-0o2, 4<-4o6 ; warp 4 publishes result
    if (g == 0) sig_fold(S, sdx[2], i, j0);
    if (g == 4) {
        sig_fold(S, sdx[6], i, j0);
        sig_store(sdx[4], S, i, j0);
    }
    __syncthreads();

    // round 3: 0<-0o4 ; write result
    if (g == 0) {
        sig_fold(S, sdx[4], i, j0);
        float* __restrict__ ob = out + (size_t)batch * SIGSZ;
        if (j0 == 0) ob[i] = S.A1;
        *(float2*)(ob + 8 + i * 8 + j0) = make_float2(S.A2[0], S.A2[1]);
        float* b3 = ob + 72 + (i * 8 + j0) * 8;
        *(float4*)(b3)      = make_float4(S.A3[0][0], S.A3[0][1], S.A3[0][2], S.A3[0][3]);
        *(float4*)(b3 + 4)  = make_float4(S.A3[0][4], S.A3[0][5], S.A3[0][6], S.A3[0][7]);
        *(float4*)(b3 + 8)  = make_float4(S.A3[1][0], S.A3[1][1], S.A3[1][2], S.A3[1][3]);
        *(float4*)(b3 + 12) = make_float4(S.A3[1][4], S.A3[1][5], S.A3[1][6], S.A3[1][7]);
    }
}

extern "C" void kernel_launch(void* const* d_in, const int* in_sizes, int n_in,
                              void* d_out, int out_size) {
    const float* path = (const float*)d_in[0];
    float* out = (float*)d_out;
    sig_kernel<<<NB, 256>>>(path, out);   // one 256-thread block per batch
}

// round 17
// speedup vs baseline: 1.1201x; 1.1201x over previous
#include <cuda_runtime.h>

// Problem constants
#define NB   512      // batches
#define NL   512      // stream length
#define NC   8        // channels
#define NSEG 8        // segments per batch (Chen-associative split)
#define SEGLEN 64     // increments per segment (last padded with one zero dx)
#define SIGSZ 584     // 8 + 64 + 512
#define NINC (NL - 1) // 511
#define SBUF 592      // padded per-segment smem buffer (>= 584 and >= SEGLEN*NC)

// ---------------------------------------------------------------------------
// Fused signature kernel: 1 block = 1 batch, 128 threads = 4 warps.
// Warp g covers TWO segments: lanes 0-15 -> segment 2g, lanes 16-31 -> 2g+1.
// Lane owns FOUR pairs (i, j0..j0+3): i = (lane&15)>>1, j0 = (lane&1)*4.
// Per warp-step: 4 LDS (d0,d1 .128 broadcast, dxi .32, dxj .128) + 43 FMA
// covering 2 segment-steps. Per step (old state RHS), m/n shared over 4 pairs:
//   m = dxi/6 + S1h ; n = 3m - S1h (= dxi/2 + S1)
//   c_p = dxj_p*m + S2_p ; S2_p += dxj_p*n ; S3[p][k] += c_p*dx_k ; S1h += dxi/2
// Segment 7 has 63 real increments; its 64th is zeroed (identity element).
// Then the 8 partial signatures tree-fold in smem (3 rounds); warp 0 writes.
// ---------------------------------------------------------------------------

struct SigRegs4 {
    float A1;        // A1[i]
    float A2[4];     // A2[i, j0..j0+3]
    float A3[4][8];  // A3[i, j0+p, 0..7]
};

__device__ __forceinline__ void sig_store4(float* __restrict__ sb,
                                           const SigRegs4& S, int i, int j0) {
    if (j0 == 0) sb[i] = S.A1;
    *(float4*)(sb + 8 + i * 8 + j0) = make_float4(S.A2[0], S.A2[1], S.A2[2], S.A2[3]);
    float* b3 = sb + 72 + (i * 8 + j0) * 8;
    #pragma unroll
    for (int p = 0; p < 4; p++) {
        *(float4*)(b3 + p * 8)     = make_float4(S.A3[p][0], S.A3[p][1], S.A3[p][2], S.A3[p][3]);
        *(float4*)(b3 + p * 8 + 4) = make_float4(S.A3[p][4], S.A3[p][5], S.A3[p][6], S.A3[p][7]);
    }
}

// Chen fold, 4-pair layout (B in standard sig layout in smem; old A on RHS)
__device__ __forceinline__ void sig_fold4(SigRegs4& S, const float* __restrict__ sb,
                                          int i, int j0) {
    const float  B1i = sb[i];
    const float4 B1j = *(const float4*)(sb + j0);
    const float4 B2q = *(const float4*)(sb + 8 + i * 8 + j0);
    float4 x0 = *(const float4*)(sb);
    float4 x1 = *(const float4*)(sb + 4);
    float b1v[8] = {x0.x, x0.y, x0.z, x0.w, x1.x, x1.y, x1.z, x1.w};

    // B2 rows j0..j0+3 = 32 contiguous floats; B3 rows (i,j0..j0+3) likewise
    float b2v[4][8], b3v[4][8];
    const float* b2p = sb + 8 + j0 * 8;
    const float* b3p = sb + 72 + (i * 8 + j0) * 8;
    #pragma unroll
    for (int p = 0; p < 4; p++) {
        float4 a = *(const float4*)(b2p + p * 8);
        float4 b = *(const float4*)(b2p + p * 8 + 4);
        b2v[p][0]=a.x; b2v[p][1]=a.y; b2v[p][2]=a.z; b2v[p][3]=a.w;
        b2v[p][4]=b.x; b2v[p][5]=b.y; b2v[p][6]=b.z; b2v[p][7]=b.w;
        float4 c = *(const float4*)(b3p + p * 8);
        float4 d = *(const float4*)(b3p + p * 8 + 4);
        b3v[p][0]=c.x; b3v[p][1]=c.y; b3v[p][2]=c.z; b3v[p][3]=c.w;
        b3v[p][4]=d.x; b3v[p][5]=d.y; b3v[p][6]=d.z; b3v[p][7]=d.w;
    }

    const float B1jv[4] = {B1j.x, B1j.y, B1j.z, B1j.w};
    const float B2qv[4] = {B2q.x, B2q.y, B2q.z, B2q.w};
    #pragma unroll
    for (int p = 0; p < 4; p++) {
        #pragma unroll
        for (int k = 0; k < 8; k++)  // uses OLD A1, A2
            S.A3[p][k] = fmaf(S.A1, b2v[p][k],
                         fmaf(S.A2[p], b1v[k], S.A3[p][k] + b3v[p][k]));
        S.A2[p] = fmaf(S.A1, B1jv[p], S.A2[p] + B2qv[p]);
    }
    S.A1 = S.A1 + B1i;
}

__global__ __launch_bounds__(128) void sig_kernel(const float* __restrict__ path,
                                                  float* __restrict__ out) {
    // Per-segment buffer: 512 increment floats during scan, 584-float sig
    // during the fold. 8 * 592 * 4B = 18.9 KB.
    __shared__ __align__(16) float sdx[NSEG][SBUF];

    const int tid  = threadIdx.x;
    const int g    = tid >> 5;          // warp (0..3)
    const int lane = tid & 31;
    const int half = lane >> 4;         // which segment of this warp's pair
    const int hl   = lane & 15;
    const int i    = hl >> 1;
    const int j0   = (hl & 1) << 2;
    const int seg  = 2 * g + half;      // global segment 0..7
    const int batch = blockIdx.x;

    // ---- stage increments for BOTH of this warp's segments (128 steps) ----
    {
        const float4* __restrict__ pb4 =
            (const float4*)(path + (size_t)batch * NL * NC + (size_t)(2 * g * SEGLEN) * NC);
        for (int v = lane; v < 2 * SEGLEN * 2; v += 32) {
            const int st    = v >> 1;                 // local step 0..127
            const int gstep = 2 * g * SEGLEN + st;    // global step
            float4 val;
            if (gstep < NINC) {
                float4 a = pb4[v];
                float4 b = pb4[v + 2];                // next step, same channels
                val = make_float4(b.x - a.x, b.y - a.y, b.z - a.z, b.w - a.w);
            } else {
                val = make_float4(0.f, 0.f, 0.f, 0.f);  // identity increment
            }
            ((float4*)sdx[2 * g + (st >> 6)])[((st & 63) << 1) | (v & 1)] = val;
        }
    }
    __syncwarp();

    // ---- sequential scan (half-warp per segment, lockstep) ----
    float S1h = 0.f;
    float S2[4];
    float S3[4][8];
    #pragma unroll
    for (int p = 0; p < 4; p++) {
        S2[p] = 0.f;
        #pragma unroll
        for (int k = 0; k < 8; k++) S3[p][k] = 0.f;
    }

    const float* __restrict__ dxp = sdx[seg];
    #pragma unroll 2
    for (int s = 0; s < SEGLEN; s++) {
        const float4 d0  = *(const float4*)(dxp + s * 8);
        const float4 d1  = *(const float4*)(dxp + s * 8 + 4);
        const float  dxi = dxp[s * 8 + i];
        const float4 dxj = *(const float4*)(dxp + s * 8 + j0);

        const float m = fmaf(dxi, 0.16666666666666666f, S1h);
        const float n = fmaf(3.0f, m, -S1h);          // dxi/2 + S1
        const float c0 = fmaf(dxj.x, m, S2[0]);
        const float c1 = fmaf(dxj.y, m, S2[1]);
        const float c2 = fmaf(dxj.z, m, S2[2]);
        const float c3 = fmaf(dxj.w, m, S2[3]);
        S2[0] = fmaf(dxj.x, n, S2[0]);
        S2[1] = fmaf(dxj.y, n, S2[1]);
        S2[2] = fmaf(dxj.z, n, S2[2]);
        S2[3] = fmaf(dxj.w, n, S2[3]);

        S3[0][0] = fmaf(c0, d0.x, S3[0][0]);
        S3[0][1] = fmaf(c0, d0.y, S3[0][1]);
        S3[0][2] = fmaf(c0, d0.z, S3[0][2]);
        S3[0][3] = fmaf(c0, d0.w, S3[0][3]);
        S3[0][4] = fmaf(c0, d1.x, S3[0][4]);
        S3[0][5] = fmaf(c0, d1.y, S3[0][5]);
        S3[0][6] = fmaf(c0, d1.z, S3[0][6]);
        S3[0][7] = fmaf(c0, d1.w, S3[0][7]);
        S3[1][0] = fmaf(c1, d0.x, S3[1][0]);
        S3[1][1] = fmaf(c1, d0.y, S3[1][1]);
        S3[1][2] = fmaf(c1, d0.z, S3[1][2]);
        S3[1][3] = fmaf(c1, d0.w, S3[1][3]);
        S3[1][4] = fmaf(c1, d1.x, S3[1][4]);
        S3[1][5] = fmaf(c1, d1.y, S3[1][5]);
        S3[1][6] = fmaf(c1, d1.z, S3[1][6]);
        S3[1][7] = fmaf(c1, d1.w, S3[1][7]);
        S3[2][0] = fmaf(c2, d0.x, S3[2][0]);
        S3[2][1] = fmaf(c2, d0.y, S3[2][1]);
        S3[2][2] = fmaf(c2, d0.z, S3[2][2]);
        S3[2][3] = fmaf(c2, d0.w, S3[2][3]);
        S3[2][4] = fmaf(c2, d1.x, S3[2][4]);
        S3[2][5] = fmaf(c2, d1.y, S3[2][5]);
        S3[2][6] = fmaf(c2, d1.z, S3[2][6]);
        S3[2][7] = fmaf(c2, d1.w, S3[2][7]);
        S3[3][0] = fmaf(c3, d0.x, S3[3][0]);
        S3[3][1] = fmaf(c3, d0.y, S3[3][1]);
        S3[3][2] = fmaf(c3, d0.z, S3[3][2]);
        S3[3][3] = fmaf(c3, d0.w, S3[3][3]);
        S3[3][4] = fmaf(c3, d1.x, S3[3][4]);
        S3[3][5] = fmaf(c3, d1.y, S3[3][5]);
        S3[3][6] = fmaf(c3, d1.z, S3[3][6]);
        S3[3][7] = fmaf(c3, d1.w, S3[3][7]);

        S1h = fmaf(0.5f, dxi, S1h);
    }

    SigRegs4 S;
    S.A1 = 2.f * S1h;
    #pragma unroll
    for (int p = 0; p < 4; p++) {
        S.A2[p] = S2[p];
        #pragma unroll
        for (int k = 0; k < 8; k++) S.A3[p][k] = S3[p][k];
    }

    // all lanes done reading increments before any publish overwrites buffers
    __syncwarp();

    // ---- fold the warp's two halves: lower <- lower o upper ----
    if (half == 1) sig_store4(sdx[seg], S, i, j0);
    __syncwarp();
    if (half == 0) {
        sig_fold4(S, sdx[2 * g + 1], i, j0);
        // warps 1,3 publish their folded pair for the cross-warp rounds
        if (g & 1) sig_store4(sdx[2 * g], S, i, j0);
    }
    __syncthreads();

    // round 2: w0 <- w0 o w1(pair at sdx[2]), w2 <- w2 o w3(pair at sdx[6])
    if (half == 0 && g == 0) sig_fold4(S, sdx[2], i, j0);
    if (half == 0 && g == 2) {
        sig_fold4(S, sdx[6], i, j0);
        sig_store4(sdx[4], S, i, j0);
    }
    __syncthreads();

    // round 3: w0 <- w0 o w2 ; write result
    if (half == 0 && g == 0) {
        sig_fold4(S, sdx[4], i, j0);
        float* __restrict__ ob = out + (size_t)batch * SIGSZ;
        if (j0 == 0) ob[i] = S.A1;
        *(float4*)(ob + 8 + i * 8 + j0) = make_float4(S.A2[0], S.A2[1], S.A2[2], S.A2[3]);
        float* b3 = ob + 72 + (i * 8 + j0) * 8;
        #pragma unroll
        for (int p = 0; p < 4; p++) {
            *(float4*)(b3 + p * 8)     = make_float4(S.A3[p][0], S.A3[p][1], S.A3[p][2], S.A3[p][3]);
            *(float4*)(b3 + p * 8 + 4) = make_float4(S.A3[p][4], S.A3[p][5], S.A3[p][6], S.A3[p][7]);
        }
    }
}

extern "C" void kernel_launch(void* const* d_in, const int* in_sizes, int n_in,
                              void* d_out, int out_size) {
    const float* path = (const float*)d_in[0];
    float* out = (float*)d_out;
    sig_kernel<<<NB, 128>>>(path, out);   // one 128-thread block per batch
}